// round 1
// baseline (speedup 1.0000x reference)
#include <cuda_runtime.h>

#define D 64
#define ALPHA 0.2f
#define MAX_N 131072
#define MAX_E 2200000

// Scratch (static device globals — no runtime allocation)
__device__ int    g_cnt[MAX_N];
__device__ int    g_rowptr[MAX_N + 1];
__device__ int    g_blocksum[512];
__device__ int    g_col[MAX_E];
__device__ float2 g_w[MAX_E];     // per-edge exp(leakyrelu(score)) for both heads
__device__ float2 g_s1[MAX_N];    // per-node source-side scores (head0, head1)
__device__ float2 g_s2[MAX_N];    // per-node dest-side scores

__global__ void k_zero_cnt(int n) {
    int i = blockIdx.x * blockDim.x + threadIdx.x;
    if (i < n) g_cnt[i] = 0;
}

__global__ void k_hist(const int* __restrict__ row, int E) {
    int i = blockIdx.x * blockDim.x + threadIdx.x;
    if (i < E) atomicAdd(&g_cnt[row[i]], 1);
}

// One warp per node: s1[h] = (x*W[h])·a[h][:64], s2[h] = (x*W[h])·a[h][64:]
__global__ void k_precompute(const float* __restrict__ x,
                             const float* __restrict__ W,
                             const float* __restrict__ a, int n) {
    int warp = (blockIdx.x * blockDim.x + threadIdx.x) >> 5;
    int lane = threadIdx.x & 31;
    if (warp >= n) return;
    float2 xv = reinterpret_cast<const float2*>(x)[warp * 32 + lane];
    int l2 = lane * 2;
    float h00 = xv.x * W[l2],      h01 = xv.y * W[l2 + 1];
    float h10 = xv.x * W[64 + l2], h11 = xv.y * W[64 + l2 + 1];
    float s10 = h00 * a[l2]       + h01 * a[l2 + 1];
    float s20 = h00 * a[64 + l2]  + h01 * a[64 + l2 + 1];
    float s11 = h10 * a[128 + l2] + h11 * a[128 + l2 + 1];
    float s21 = h10 * a[192 + l2] + h11 * a[192 + l2 + 1];
    #pragma unroll
    for (int o = 16; o; o >>= 1) {
        s10 += __shfl_xor_sync(0xffffffffu, s10, o);
        s20 += __shfl_xor_sync(0xffffffffu, s20, o);
        s11 += __shfl_xor_sync(0xffffffffu, s11, o);
        s21 += __shfl_xor_sync(0xffffffffu, s21, o);
    }
    if (lane == 0) {
        g_s1[warp] = make_float2(s10, s11);
        g_s2[warp] = make_float2(s20, s21);
    }
}

// 3-kernel exclusive scan of g_cnt -> g_rowptr
__global__ void k_scan1(int n) {
    __shared__ int sh[512];
    int t = threadIdx.x;
    int i = blockIdx.x * 512 + t;
    int v = (i < n) ? g_cnt[i] : 0;
    sh[t] = v;
    __syncthreads();
    #pragma unroll
    for (int o = 1; o < 512; o <<= 1) {
        int tmp = (t >= o) ? sh[t - o] : 0;
        __syncthreads();
        sh[t] += tmp;
        __syncthreads();
    }
    if (i < n) g_rowptr[i] = sh[t] - v;   // local exclusive
    if (t == 511) g_blocksum[blockIdx.x] = sh[511];
}

__global__ void k_scan2(int nb) {
    __shared__ int sh[512];
    int t = threadIdx.x;
    int v = (t < nb) ? g_blocksum[t] : 0;
    sh[t] = v;
    __syncthreads();
    #pragma unroll
    for (int o = 1; o < 512; o <<= 1) {
        int tmp = (t >= o) ? sh[t - o] : 0;
        __syncthreads();
        sh[t] += tmp;
        __syncthreads();
    }
    if (t < nb) g_blocksum[t] = sh[t] - v;  // exclusive block bases
}

__global__ void k_scan3(int n, int E) {
    int i = blockIdx.x * 512 + threadIdx.x;
    if (i < n) g_rowptr[i] += g_blocksum[blockIdx.x];
    if (i == n) g_rowptr[n] = E;
}

// Edge-parallel: place edge into CSR slot, precompute both head weights.
__global__ void k_scatter(const int* __restrict__ row,
                          const int* __restrict__ col, int E) {
    int i = blockIdx.x * blockDim.x + threadIdx.x;
    if (i >= E) return;
    int r = row[i], c = col[i];
    int pos = g_rowptr[r] + atomicAdd(&g_cnt[r], 1);
    float2 s1 = g_s1[r];
    float2 s2 = g_s2[c];
    float sc0 = s1.x + s2.x;
    float sc1 = s1.y + s2.y;
    float w0 = __expf(sc0 > 0.f ? sc0 : ALPHA * sc0);
    float w1 = __expf(sc1 > 0.f ? sc1 : ALPHA * sc1);
    g_col[pos] = c;
    g_w[pos] = make_float2(w0, w1);
}

// One warp per node: gather x[col] rows (L2-resident), register accumulate,
// softmax-normalize, mean over the 2 heads.
__global__ void k_aggregate(const float* __restrict__ x,
                            float* __restrict__ out, int n) {
    int warp = (blockIdx.x * blockDim.x + threadIdx.x) >> 5;
    int lane = threadIdx.x & 31;
    if (warp >= n) return;
    int beg = g_rowptr[warp];
    int end = g_rowptr[warp + 1];
    const float2* x2 = reinterpret_cast<const float2*>(x);
    float acc00 = 0.f, acc01 = 0.f, acc10 = 0.f, acc11 = 0.f;
    float rs0 = 0.f, rs1 = 0.f;
    for (int e = beg; e < end; e++) {
        int c = g_col[e];
        float2 w = g_w[e];
        float2 xv = x2[c * 32 + lane];
        acc00 += w.x * xv.x; acc01 += w.x * xv.y;
        acc10 += w.y * xv.x; acc11 += w.y * xv.y;
        rs0 += w.x; rs1 += w.y;
    }
    float inv0 = 0.5f / rs0, inv1 = 0.5f / rs1;
    float2 o;
    o.x = acc00 * inv0 + acc10 * inv1;
    o.y = acc01 * inv0 + acc11 * inv1;
    reinterpret_cast<float2*>(out)[warp * 32 + lane] = o;
}

extern "C" void kernel_launch(void* const* d_in, const int* in_sizes, int n_in,
                              void* d_out, int out_size) {
    const float* x  = (const float*)d_in[0];
    const int*   ei = (const int*)d_in[1];
    const float* W  = (const float*)d_in[2];
    const float* a  = (const float*)d_in[3];
    float* out = (float*)d_out;

    int n = in_sizes[0] / D;
    int E = in_sizes[1] / 2;
    const int* row = ei;
    const int* col = ei + E;

    const int T = 256;
    int nbN = (n + T - 1) / T;
    int nbE = (E + T - 1) / T;
    int nbW = (n * 32 + T - 1) / T;      // one warp per node
    int nbS = (n + 511) / 512;

    k_zero_cnt<<<nbN, T>>>(n);
    k_hist<<<nbE, T>>>(row, E);
    k_precompute<<<nbW, T>>>(x, W, a, n);
    k_scan1<<<nbS, 512>>>(n);
    k_scan2<<<1, 512>>>(nbS);
    k_scan3<<<(n + 512) / 512, 512>>>(n, E);
    k_zero_cnt<<<nbN, T>>>(n);
    k_scatter<<<nbE, T>>>(row, col, E);
    k_aggregate<<<nbW, T>>>(x, out, n);
}